// round 3
// baseline (speedup 1.0000x reference)
#include <cuda_runtime.h>

#define N_NODES 100000
#define N_EDGES 1600000
#define F 128
#define ROWS_PER_WARP 8
#define WARPS_PER_BLK 8
#define THREADS_PER_BLK (WARPS_PER_BLK * 32)
#define LAYER_GRID 444

// smem: W (128*128) + bias (128) + t-stage (8 warps * 8 rows * 128)
#define SMEM_FLOATS (F * F + F + WARPS_PER_BLK * ROWS_PER_WARP * F)
#define SMEM_BYTES (SMEM_FLOATS * 4)

typedef unsigned long long u64;

// packed f32x2 helpers (Blackwell FFMA2 — only reachable via PTX fma.rn.f32x2)
__device__ __forceinline__ u64 pk2(float lo, float hi) {
    u64 r; asm("mov.b64 %0, {%1, %2};" : "=l"(r) : "f"(lo), "f"(hi)); return r;
}
__device__ __forceinline__ void upk2(u64 v, float& lo, float& hi) {
    asm("mov.b64 {%0, %1}, %2;" : "=f"(lo), "=f"(hi) : "l"(v));
}
__device__ __forceinline__ void fma2(u64& d, u64 a, u64 b) {
    asm("fma.rn.f32x2 %0, %1, %2, %0;" : "+l"(d) : "l"(a), "l"(b));
}

// ---------------- scratch (no allocations allowed) ----------------
__device__ int   g_counts[N_NODES];
__device__ int   g_off[N_NODES + 1];
__device__ int   g_cursor[N_NODES];
__device__ int   g_bsum[128];
__device__ float g_inv[N_NODES];
__device__ int   g_csr[N_EDGES];
__device__ float g_h0[(size_t)N_NODES * F];
__device__ float g_h1[(size_t)N_NODES * F];

// ---------------- preprocessing: build CSR by dst ----------------
__global__ void k_zero() {
    int i = blockIdx.x * blockDim.x + threadIdx.x;
    if (i < N_NODES) g_counts[i] = 0;
}

__global__ void k_hist(const int* __restrict__ dst) {
    int e = blockIdx.x * blockDim.x + threadIdx.x;
    if (e < N_EDGES) atomicAdd(&g_counts[dst[e]], 1);
}

__global__ void k_scan_part() {
    __shared__ int sh[1024];
    int t = threadIdx.x;
    int j = blockIdx.x * 1024 + t;
    int v = (j < N_NODES) ? g_counts[j] : 0;
    sh[t] = v;
    __syncthreads();
    for (int d = 1; d < 1024; d <<= 1) {
        int x = (t >= d) ? sh[t - d] : 0;
        __syncthreads();
        sh[t] += x;
        __syncthreads();
    }
    int incl = sh[t];
    if (j <= N_NODES) g_off[j] = incl - v;     // exclusive within block
    if (t == 1023) g_bsum[blockIdx.x] = incl;  // block total
}

// parallel top-level scan over <=128 block sums (was 7.9us serial)
__global__ void k_scan_top(int nblocks) {
    __shared__ int sh[128];
    int t = threadIdx.x;
    int v = (t < nblocks) ? g_bsum[t] : 0;
    sh[t] = v;
    __syncthreads();
    for (int d = 1; d < 128; d <<= 1) {
        int x = (t >= d) ? sh[t - d] : 0;
        __syncthreads();
        sh[t] += x;
        __syncthreads();
    }
    if (t < nblocks) g_bsum[t] = sh[t] - v;   // exclusive
}

__global__ void k_scan_add() {
    int j = blockIdx.x * blockDim.x + threadIdx.x;
    if (j <= N_NODES) {
        int o = g_off[j] + g_bsum[j >> 10];
        g_off[j] = o;
        if (j < N_NODES) {
            g_cursor[j] = o;
            int c = g_counts[j];
            g_inv[j] = 1.0f / (float)(c > 0 ? c : 1);
        }
    }
}

__global__ void k_scatter(const int* __restrict__ src, const int* __restrict__ dst) {
    int e = blockIdx.x * blockDim.x + threadIdx.x;
    if (e < N_EDGES) {
        int d = dst[e];
        int pos = atomicAdd(&g_cursor[d], 1);
        g_csr[pos] = src[e];
    }
}

// ---------------- fused layer: mean-agg + (h+agg)@W + b (+relu) ----------------
__global__ __launch_bounds__(THREADS_PER_BLK, 3)
void k_layer(const float* __restrict__ hin, const float* __restrict__ Wg,
             const float* __restrict__ bias, float* __restrict__ hout,
             int do_relu) {
    extern __shared__ float smem[];
    float* sW = smem;                 // F*F
    float* sb = smem + F * F;         // F
    float* sT = sb + F;               // WARPS_PER_BLK * ROWS_PER_WARP * F

    int tid = threadIdx.x;
    // cooperative load of W + bias
    for (int i = tid; i < (F * F) / 4; i += blockDim.x)
        ((float4*)sW)[i] = ((const float4*)Wg)[i];
    if (tid < F) sb[tid] = bias[tid];
    __syncthreads();

    int lane = tid & 31;
    int wId = tid >> 5;
    int gwarp = blockIdx.x * WARPS_PER_BLK + wId;
    int nwarps = gridDim.x * WARPS_PER_BLK;
    float* myT = sT + wId * (ROWS_PER_WARP * F);
    float4 bv = ((const float4*)sb)[lane];
    u64 bA = pk2(bv.x, bv.y);
    u64 bB = pk2(bv.z, bv.w);

    const int NGRP = N_NODES / ROWS_PER_WARP;  // 12500, exact

    for (int grp = gwarp; grp < NGRP; grp += nwarps) {
        int row0 = grp * ROWS_PER_WARP;

        // ---- phase 1: aggregate + stage t = h + mean_neighbors(h) ----
        __syncwarp();
        #pragma unroll 1
        for (int r = 0; r < ROWS_PER_WARP; ++r) {
            int row = row0 + r;
            int e = g_off[row];
            int e1 = g_off[row + 1];
            float4 acc = make_float4(0.f, 0.f, 0.f, 0.f);
            for (; e + 4 <= e1; e += 4) {
                int s0 = g_csr[e + 0], s1 = g_csr[e + 1];
                int s2 = g_csr[e + 2], s3 = g_csr[e + 3];
                float4 v0 = *(const float4*)(hin + (size_t)s0 * F + lane * 4);
                float4 v1 = *(const float4*)(hin + (size_t)s1 * F + lane * 4);
                float4 v2 = *(const float4*)(hin + (size_t)s2 * F + lane * 4);
                float4 v3 = *(const float4*)(hin + (size_t)s3 * F + lane * 4);
                acc.x += (v0.x + v1.x) + (v2.x + v3.x);
                acc.y += (v0.y + v1.y) + (v2.y + v3.y);
                acc.z += (v0.z + v1.z) + (v2.z + v3.z);
                acc.w += (v0.w + v1.w) + (v2.w + v3.w);
            }
            for (; e < e1; ++e) {
                int s = g_csr[e];
                float4 v = *(const float4*)(hin + (size_t)s * F + lane * 4);
                acc.x += v.x; acc.y += v.y; acc.z += v.z; acc.w += v.w;
            }
            float sc = g_inv[row];
            float4 hv = *(const float4*)(hin + (size_t)row * F + lane * 4);
            float4 t;
            t.x = fmaf(acc.x, sc, hv.x);
            t.y = fmaf(acc.y, sc, hv.y);
            t.z = fmaf(acc.z, sc, hv.z);
            t.w = fmaf(acc.w, sc, hv.w);
            *(float4*)(myT + r * F + lane * 4) = t;
        }
        __syncwarp();

        // ---- phase 2: out = t @ W + b, packed f32x2 (FFMA2) ----
        // oA[r] = (o[r].x, o[r].y), oB[r] = (o[r].z, o[r].w)
        u64 oA[ROWS_PER_WARP], oB[ROWS_PER_WARP];
        #pragma unroll
        for (int r = 0; r < ROWS_PER_WARP; ++r) { oA[r] = bA; oB[r] = bB; }

        #pragma unroll 4
        for (int kk = 0; kk < F / 4; ++kk) {
            // weight rows come out of LDS already column-pair packed
            ulonglong2 w0 = ((const ulonglong2*)(sW + (4 * kk + 0) * F))[lane];
            ulonglong2 w1 = ((const ulonglong2*)(sW + (4 * kk + 1) * F))[lane];
            ulonglong2 w2 = ((const ulonglong2*)(sW + (4 * kk + 2) * F))[lane];
            ulonglong2 w3 = ((const ulonglong2*)(sW + (4 * kk + 3) * F))[lane];
            #pragma unroll
            for (int r = 0; r < ROWS_PER_WARP; ++r) {
                float4 a = *(const float4*)(myT + r * F + 4 * kk);  // broadcast
                u64 ax = pk2(a.x, a.x);
                u64 ay = pk2(a.y, a.y);
                u64 az = pk2(a.z, a.z);
                u64 aw = pk2(a.w, a.w);
                fma2(oA[r], ax, w0.x); fma2(oB[r], ax, w0.y);
                fma2(oA[r], ay, w1.x); fma2(oB[r], ay, w1.y);
                fma2(oA[r], az, w2.x); fma2(oB[r], az, w2.y);
                fma2(oA[r], aw, w3.x); fma2(oB[r], aw, w3.y);
            }
        }

        #pragma unroll
        for (int r = 0; r < ROWS_PER_WARP; ++r) {
            float4 v;
            upk2(oA[r], v.x, v.y);
            upk2(oB[r], v.z, v.w);
            if (do_relu) {
                v.x = fmaxf(v.x, 0.f); v.y = fmaxf(v.y, 0.f);
                v.z = fmaxf(v.z, 0.f); v.w = fmaxf(v.w, 0.f);
            }
            *(float4*)(hout + (size_t)(row0 + r) * F + lane * 4) = v;
        }
    }
}

// ---------------- launch ----------------
extern "C" void kernel_launch(void* const* d_in, const int* in_sizes, int n_in,
                              void* d_out, int out_size) {
    const float* x  = (const float*)d_in[0];
    const float* W1 = (const float*)d_in[1];
    const float* b1 = (const float*)d_in[2];
    const float* W2 = (const float*)d_in[3];
    const float* b2 = (const float*)d_in[4];
    const float* W3 = (const float*)d_in[5];
    const float* b3 = (const float*)d_in[6];
    const int* esrc = (const int*)d_in[7];
    const int* edst = (const int*)d_in[8];
    float* out = (float*)d_out;

    cudaFuncSetAttribute(k_layer, cudaFuncAttributeMaxDynamicSharedMemorySize,
                         SMEM_BYTES);

    void *ph0 = nullptr, *ph1 = nullptr;
    cudaGetSymbolAddress(&ph0, g_h0);
    cudaGetSymbolAddress(&ph1, g_h1);
    float* h0 = (float*)ph0;
    float* h1 = (float*)ph1;

    int scan_blocks = (N_NODES + 1 + 1023) / 1024;  // 98
    k_zero<<<(N_NODES + 255) / 256, 256>>>();
    k_hist<<<(N_EDGES + 255) / 256, 256>>>(edst);
    k_scan_part<<<scan_blocks, 1024>>>();
    k_scan_top<<<1, 128>>>(scan_blocks);
    k_scan_add<<<(N_NODES + 1 + 255) / 256, 256>>>();
    k_scatter<<<(N_EDGES + 255) / 256, 256>>>(esrc, edst);

    k_layer<<<LAYER_GRID, THREADS_PER_BLK, SMEM_BYTES>>>(x,  W1, b1, h0, 1);
    k_layer<<<LAYER_GRID, THREADS_PER_BLK, SMEM_BYTES>>>(h0, W2, b2, h1, 1);
    k_layer<<<LAYER_GRID, THREADS_PER_BLK, SMEM_BYTES>>>(h1, W3, b3, out, 0);
}

// round 6
// speedup vs baseline: 1.2143x; 1.2143x over previous
#include <cuda_runtime.h>

#define N_NODES 100000
#define N_EDGES 1600000
#define F 128
#define ROWS_PER_WARP 4
#define WARPS_PER_BLK 8
#define THREADS_PER_BLK (WARPS_PER_BLK * 32)
#define LAYER_GRID 296
#define NGRP (N_NODES / ROWS_PER_WARP)   // 25000 exact

// smem: W (128*128) + bias (128) + t-stage (8 warps * 2 bufs * 4 rows * 128)
#define SMEM_FLOATS (F * F + F + WARPS_PER_BLK * 2 * ROWS_PER_WARP * F)
#define SMEM_BYTES (SMEM_FLOATS * 4)

// ---------------- scratch (no allocations allowed) ----------------
__device__ int   g_counts[N_NODES];
__device__ int   g_off[N_NODES + 1];
__device__ int   g_cursor[N_NODES];
__device__ int   g_bsum[128];
__device__ float g_inv[N_NODES];
__device__ int   g_csr[N_EDGES];
__device__ float g_h0[(size_t)N_NODES * F];
__device__ float g_h1[(size_t)N_NODES * F];

// ---------------- preprocessing: build CSR by dst ----------------
__global__ void k_zero() {
    int i = blockIdx.x * blockDim.x + threadIdx.x;
    if (i < N_NODES) g_counts[i] = 0;
}

__global__ void k_hist(const int* __restrict__ dst) {
    int e = blockIdx.x * blockDim.x + threadIdx.x;
    if (e < N_EDGES) atomicAdd(&g_counts[dst[e]], 1);
}

__global__ void k_scan_part() {
    __shared__ int sh[1024];
    int t = threadIdx.x;
    int j = blockIdx.x * 1024 + t;
    int v = (j < N_NODES) ? g_counts[j] : 0;
    sh[t] = v;
    __syncthreads();
    for (int d = 1; d < 1024; d <<= 1) {
        int x = (t >= d) ? sh[t - d] : 0;
        __syncthreads();
        sh[t] += x;
        __syncthreads();
    }
    int incl = sh[t];
    if (j <= N_NODES) g_off[j] = incl - v;     // exclusive within block
    if (t == 1023) g_bsum[blockIdx.x] = incl;  // block total
}

__global__ void k_scan_top(int nblocks) {
    __shared__ int sh[128];
    int t = threadIdx.x;
    int v = (t < nblocks) ? g_bsum[t] : 0;
    sh[t] = v;
    __syncthreads();
    for (int d = 1; d < 128; d <<= 1) {
        int x = (t >= d) ? sh[t - d] : 0;
        __syncthreads();
        sh[t] += x;
        __syncthreads();
    }
    if (t < nblocks) g_bsum[t] = sh[t] - v;   // exclusive
}

__global__ void k_scan_add() {
    int j = blockIdx.x * blockDim.x + threadIdx.x;
    if (j <= N_NODES) {
        int o = g_off[j] + g_bsum[j >> 10];
        g_off[j] = o;
        if (j < N_NODES) {
            g_cursor[j] = o;
            int c = g_counts[j];
            g_inv[j] = 1.0f / (float)(c > 0 ? c : 1);
        }
    }
}

__global__ void k_scatter(const int* __restrict__ src, const int* __restrict__ dst) {
    int e = blockIdx.x * blockDim.x + threadIdx.x;
    if (e < N_EDGES) {
        int d = dst[e];
        int pos = atomicAdd(&g_cursor[d], 1);
        g_csr[pos] = src[e];
    }
}

// ---------------- fused layer: mean-agg + (h+agg)@W + b (+relu) ----------------
// Software-pipelined (depth 2) with parity stagger: even warps do
// [agg(next); gemm(cur)], odd warps do [gemm(cur); agg(next)] so at any
// instant ~half the warps drive L2 and half drive the FMA pipe.
__global__ __launch_bounds__(THREADS_PER_BLK)
void k_layer(const float* __restrict__ hin, const float* __restrict__ Wg,
             const float* __restrict__ bias, float* __restrict__ hout,
             int do_relu) {
    extern __shared__ float smem[];
    float* sW = smem;                 // F*F
    float* sb = smem + F * F;         // F
    float* sT = sb + F;               // WARPS_PER_BLK * 2 * ROWS_PER_WARP * F

    int tid = threadIdx.x;
    for (int i = tid; i < (F * F) / 4; i += blockDim.x)
        ((float4*)sW)[i] = ((const float4*)Wg)[i];
    if (tid < F) sb[tid] = bias[tid];
    __syncthreads();

    int lane = tid & 31;
    int wId = tid >> 5;
    int gwarp = blockIdx.x * WARPS_PER_BLK + wId;
    int nwarps = gridDim.x * WARPS_PER_BLK;
    float* buf0 = sT + wId * (2 * ROWS_PER_WARP * F);
    float* buf1 = buf0 + ROWS_PER_WARP * F;
    float4 bv = ((const float4*)sb)[lane];

    // ---- phase lambdas ----
    auto agg = [&](int grp, float* buf) {
        int row0 = grp * ROWS_PER_WARP;
        __syncwarp();
        #pragma unroll 1
        for (int r = 0; r < ROWS_PER_WARP; ++r) {
            int row = row0 + r;
            int e = g_off[row];
            int e1 = g_off[row + 1];
            float4 acc = make_float4(0.f, 0.f, 0.f, 0.f);
            for (; e + 4 <= e1; e += 4) {
                int s0 = g_csr[e + 0], s1 = g_csr[e + 1];
                int s2 = g_csr[e + 2], s3 = g_csr[e + 3];
                float4 v0 = *(const float4*)(hin + (size_t)s0 * F + lane * 4);
                float4 v1 = *(const float4*)(hin + (size_t)s1 * F + lane * 4);
                float4 v2 = *(const float4*)(hin + (size_t)s2 * F + lane * 4);
                float4 v3 = *(const float4*)(hin + (size_t)s3 * F + lane * 4);
                acc.x += (v0.x + v1.x) + (v2.x + v3.x);
                acc.y += (v0.y + v1.y) + (v2.y + v3.y);
                acc.z += (v0.z + v1.z) + (v2.z + v3.z);
                acc.w += (v0.w + v1.w) + (v2.w + v3.w);
            }
            for (; e < e1; ++e) {
                int s = g_csr[e];
                float4 v = *(const float4*)(hin + (size_t)s * F + lane * 4);
                acc.x += v.x; acc.y += v.y; acc.z += v.z; acc.w += v.w;
            }
            float sc = g_inv[row];
            float4 hv = *(const float4*)(hin + (size_t)row * F + lane * 4);
            float4 t;
            t.x = fmaf(acc.x, sc, hv.x);
            t.y = fmaf(acc.y, sc, hv.y);
            t.z = fmaf(acc.z, sc, hv.z);
            t.w = fmaf(acc.w, sc, hv.w);
            *(float4*)(buf + r * F + lane * 4) = t;
        }
        __syncwarp();
    };

    auto gemm = [&](int grp, float* buf) {
        int row0 = grp * ROWS_PER_WARP;
        __syncwarp();
        float4 o[ROWS_PER_WARP];
        #pragma unroll
        for (int r = 0; r < ROWS_PER_WARP; ++r) o[r] = bv;

        #pragma unroll 4
        for (int kk = 0; kk < F / 4; ++kk) {
            float4 w0 = ((const float4*)(sW + (4 * kk + 0) * F))[lane];
            float4 w1 = ((const float4*)(sW + (4 * kk + 1) * F))[lane];
            float4 w2 = ((const float4*)(sW + (4 * kk + 2) * F))[lane];
            float4 w3 = ((const float4*)(sW + (4 * kk + 3) * F))[lane];
            #pragma unroll
            for (int r = 0; r < ROWS_PER_WARP; ++r) {
                float4 a = *(const float4*)(buf + r * F + 4 * kk);  // broadcast
                o[r].x += a.x * w0.x; o[r].y += a.x * w0.y;
                o[r].z += a.x * w0.z; o[r].w += a.x * w0.w;
                o[r].x += a.y * w1.x; o[r].y += a.y * w1.y;
                o[r].z += a.y * w1.z; o[r].w += a.y * w1.w;
                o[r].x += a.z * w2.x; o[r].y += a.z * w2.y;
                o[r].z += a.z * w2.z; o[r].w += a.z * w2.w;
                o[r].x += a.w * w3.x; o[r].y += a.w * w3.y;
                o[r].z += a.w * w3.z; o[r].w += a.w * w3.w;
            }
        }

        #pragma unroll
        for (int r = 0; r < ROWS_PER_WARP; ++r) {
            float4 v = o[r];
            if (do_relu) {
                v.x = fmaxf(v.x, 0.f); v.y = fmaxf(v.y, 0.f);
                v.z = fmaxf(v.z, 0.f); v.w = fmaxf(v.w, 0.f);
            }
            *(float4*)(hout + (size_t)(row0 + r) * F + lane * 4) = v;
        }
        __syncwarp();
    };

    // ---- depth-2 pipeline with parity stagger ----
    int g = gwarp;
    if (g < NGRP) {
        agg(g, buf0);
        int prev = g;
        float* pbuf = buf0;
        float* cbuf = buf1;
        int odd = wId & 1;
        for (g += nwarps; g < NGRP; g += nwarps) {
            if (odd) {
                gemm(prev, pbuf);
                agg(g, cbuf);
            } else {
                agg(g, cbuf);
                gemm(prev, pbuf);
            }
            float* tmp = pbuf; pbuf = cbuf; cbuf = tmp;
            prev = g;
        }
        gemm(prev, pbuf);
    }
}

// ---------------- launch ----------------
extern "C" void kernel_launch(void* const* d_in, const int* in_sizes, int n_in,
                              void* d_out, int out_size) {
    const float* x  = (const float*)d_in[0];
    const float* W1 = (const float*)d_in[1];
    const float* b1 = (const float*)d_in[2];
    const float* W2 = (const float*)d_in[3];
    const float* b2 = (const float*)d_in[4];
    const float* W3 = (const float*)d_in[5];
    const float* b3 = (const float*)d_in[6];
    const int* esrc = (const int*)d_in[7];
    const int* edst = (const int*)d_in[8];
    float* out = (float*)d_out;

    cudaFuncSetAttribute(k_layer, cudaFuncAttributeMaxDynamicSharedMemorySize,
                         SMEM_BYTES);

    void *ph0 = nullptr, *ph1 = nullptr;
    cudaGetSymbolAddress(&ph0, g_h0);
    cudaGetSymbolAddress(&ph1, g_h1);
    float* h0 = (float*)ph0;
    float* h1 = (float*)ph1;

    int scan_blocks = (N_NODES + 1 + 1023) / 1024;  // 98
    k_zero<<<(N_NODES + 255) / 256, 256>>>();
    k_hist<<<(N_EDGES + 255) / 256, 256>>>(edst);
    k_scan_part<<<scan_blocks, 1024>>>();
    k_scan_top<<<1, 128>>>(scan_blocks);
    k_scan_add<<<(N_NODES + 1 + 255) / 256, 256>>>();
    k_scatter<<<(N_EDGES + 255) / 256, 256>>>(esrc, edst);

    k_layer<<<LAYER_GRID, THREADS_PER_BLK, SMEM_BYTES>>>(x,  W1, b1, h0, 1);
    k_layer<<<LAYER_GRID, THREADS_PER_BLK, SMEM_BYTES>>>(h0, W2, b2, h1, 1);
    k_layer<<<LAYER_GRID, THREADS_PER_BLK, SMEM_BYTES>>>(h1, W3, b3, out, 0);
}